// round 10
// baseline (speedup 1.0000x reference)
#include <cuda_runtime.h>
#include <math.h>

#define NNODES 100000
#define FIN    128
#define HID    128
#define CLS    64
#define EMAX   2000000

// ---------------- static device scratch ----------------
__device__ float g_h   [(size_t)NNODES * HID];
__device__ float g_emb [(size_t)NNODES * HID];
__device__ float g_h2  [(size_t)NNODES * CLS];
__device__ float g_dinv[NNODES];
__device__ int   g_deg [NNODES];
__device__ int   g_incl[NNODES];
__device__ int   g_bsum[256];
__device__ int   g_rowptr[NNODES + 1];
__device__ int   g_cursor[NNODES];
__device__ int   g_csr_src[EMAX];
__device__ int   g_idx64;

// ---------------- edge-index dtype detection ----------------
__global__ void detect_idx_kernel(const void* __restrict__ ei, int E, int N) {
    if (threadIdx.x != 0 || blockIdx.x != 0) return;
    const long long* p64 = (const long long*)ei;
    int ok = 1;
    for (int i = 0; i < 128 && i < E; i++) {
        long long a = p64[i];
        long long b = p64[(size_t)E + i];
        if (a < 0 || a >= N || b < 0 || b >= N) { ok = 0; break; }
    }
    g_idx64 = ok;
}

__device__ __forceinline__ int fetch_idx(const void* __restrict__ ei, size_t i) {
    if (g_idx64) return (int)((const long long*)ei)[i];
    return ((const int*)ei)[i];
}

__global__ void zero_deg_kernel(int N) {
    int i = blockIdx.x * blockDim.x + threadIdx.x;
    if (i < N) g_deg[i] = 0;
}

__global__ void deg_kernel(const void* __restrict__ ei, int E, int N) {
    int i = blockIdx.x * blockDim.x + threadIdx.x;
    if (i >= E) return;
    int d = fetch_idx(ei, (size_t)E + i);
    if ((unsigned)d < (unsigned)N) atomicAdd(&g_deg[d], 1);
}

// ---------------- prefix scan over degrees ----------------
__global__ __launch_bounds__(1024) void scan1_kernel(int N) {
    __shared__ int sh[1024];
    int i = blockIdx.x * 1024 + threadIdx.x;
    int v = (i < N) ? g_deg[i] : 0;
    sh[threadIdx.x] = v;
    __syncthreads();
    for (int off = 1; off < 1024; off <<= 1) {
        int t = (threadIdx.x >= off) ? sh[threadIdx.x - off] : 0;
        __syncthreads();
        sh[threadIdx.x] += t;
        __syncthreads();
    }
    if (i < N) g_incl[i] = sh[threadIdx.x];
    if (threadIdx.x == 1023) g_bsum[blockIdx.x] = sh[1023];
}

__global__ __launch_bounds__(1024) void scan2_kernel(int nb) {
    __shared__ int sh[1024];
    int v = (threadIdx.x < nb) ? g_bsum[threadIdx.x] : 0;
    sh[threadIdx.x] = v;
    __syncthreads();
    for (int off = 1; off < 1024; off <<= 1) {
        int t = (threadIdx.x >= off) ? sh[threadIdx.x - off] : 0;
        __syncthreads();
        sh[threadIdx.x] += t;
        __syncthreads();
    }
    if (threadIdx.x < nb)
        g_bsum[threadIdx.x] = (threadIdx.x == 0) ? 0 : sh[threadIdx.x - 1];
}

__global__ void scan3_kernel(int N) {
    int i = blockIdx.x * blockDim.x + threadIdx.x;
    if (i >= N) return;
    int deg = g_deg[i];
    int v = g_incl[i] + g_bsum[i >> 10];
    g_rowptr[i + 1] = v;
    g_cursor[i] = v - deg;
    g_dinv[i] = rsqrtf((float)(deg + 1));
    if (i == 0) g_rowptr[0] = 0;
}

__global__ void fill_csr_kernel(const void* __restrict__ ei, int E, int N) {
    int e = blockIdx.x * blockDim.x + threadIdx.x;
    if (e >= E) return;
    int s = fetch_idx(ei, e);
    int d = fetch_idx(ei, (size_t)E + e);
    if ((unsigned)s >= (unsigned)N || (unsigned)d >= (unsigned)N) return;
    int pos = atomicAdd(&g_cursor[d], 1);
    if (pos < EMAX) g_csr_src[pos] = s;
}

// ---------------- tensor-core helpers (3xtf32) ----------------
__device__ __forceinline__ void split_tf32(float v, unsigned& hi, unsigned& lo) {
    asm("cvt.rna.tf32.f32 %0, %1;" : "=r"(hi) : "f"(v));
    float r = v - __uint_as_float(hi);
    asm("cvt.rna.tf32.f32 %0, %1;" : "=r"(lo) : "f"(r));
}

__device__ __forceinline__ void mma_tf32(float* d, const unsigned* a, const unsigned* b) {
    asm volatile(
        "mma.sync.aligned.m16n8k8.row.col.f32.tf32.tf32.f32 "
        "{%0,%1,%2,%3}, {%4,%5,%6,%7}, {%8,%9}, {%0,%1,%2,%3};"
        : "+f"(d[0]), "+f"(d[1]), "+f"(d[2]), "+f"(d[3])
        : "r"(a[0]), "r"(a[1]), "r"(a[2]), "r"(a[3]), "r"(b[0]), "r"(b[1]));
}

// ---------------- GEMM via tensor cores, 3xtf32, pre-split in smem ----------------
// C[M,NC] = A[M,128] @ B[128,NC].  Block tile 128x64, 256 thr (warps 4m x 2n),
// warp tile 32x32 (mt=2 m16, nt=4 n8), BK=8 double-buffered (smem 33.8KB < 48KB).
// tf32 hi/lo split happens ONCE at smem-store time; inner loop is LDS+MMA only.
template <int NC>
__global__ __launch_bounds__(256)
void gemm_tc(const float* __restrict__ A, const float* __restrict__ B,
             float* __restrict__ C, int M) {
    constexpr int BK = 8;
    constexpr int ASTR = 12;   // (12g+q) mod 32 covers all 32 banks for frag pattern
    constexpr int BSTR = 72;   // (8q+g) mod 32 distinct -> conflict-free
    __shared__ unsigned As_hi[2][128][ASTR], As_lo[2][128][ASTR];
    __shared__ unsigned Bs_hi[2][BK][BSTR],  Bs_lo[2][BK][BSTR];

    const int t    = threadIdx.x;
    const int lane = t & 31;
    const int grp  = lane >> 2, qid = lane & 3;
    const int warp = t >> 5;
    const int warpM = warp & 3, warpN = warp >> 2;
    const int rowBase = blockIdx.x * 128;
    const int colBase = blockIdx.y * 64;

    float acc[2][4][4];
#pragma unroll
    for (int mt = 0; mt < 2; mt++)
#pragma unroll
        for (int nt = 0; nt < 4; nt++)
#pragma unroll
            for (int k = 0; k < 4; k++) acc[mt][nt][k] = 0.f;

    float4 sa;   // A: 128 rows x 8 cols = 256 float4 -> 1 per thread
    float2 sb;   // B: 8 rows x 64 cols  = 256 float2 -> 1 per thread
    const int aRow = t >> 1, aC4 = (t & 1) * 4;
    const int bRow = t >> 5, bC2 = (t & 31) * 2;

    auto ldA = [&](int k0) {
        int r = rowBase + aRow;
        sa = (r < M) ? *(const float4*)&A[(size_t)r * 128 + k0 + aC4]
                     : make_float4(0.f, 0.f, 0.f, 0.f);
    };
    auto ldB = [&](int k0) {
        sb = *(const float2*)&B[(size_t)(k0 + bRow) * NC + colBase + bC2];
    };
    auto stStage = [&](int buf) {
        float va[4] = {sa.x, sa.y, sa.z, sa.w};
#pragma unroll
        for (int j = 0; j < 4; j++)
            split_tf32(va[j], As_hi[buf][aRow][aC4 + j], As_lo[buf][aRow][aC4 + j]);
        split_tf32(sb.x, Bs_hi[buf][bRow][bC2],     Bs_lo[buf][bRow][bC2]);
        split_tf32(sb.y, Bs_hi[buf][bRow][bC2 + 1], Bs_lo[buf][bRow][bC2 + 1]);
    };

    ldA(0); ldB(0);
    stStage(0);
    __syncthreads();

    for (int stage = 0; stage < 128 / BK; stage++) {
        const int buf = stage & 1;
        if (stage + 1 < 128 / BK) { ldA((stage + 1) * BK); ldB((stage + 1) * BK); }
        {
            unsigned ah[2][4], al[2][4], bh[4][2], bl[4][2];
#pragma unroll
            for (int mt = 0; mt < 2; mt++) {
                int r0 = warpM * 32 + mt * 16 + grp;
                ah[mt][0] = As_hi[buf][r0][qid];          al[mt][0] = As_lo[buf][r0][qid];
                ah[mt][1] = As_hi[buf][r0 + 8][qid];      al[mt][1] = As_lo[buf][r0 + 8][qid];
                ah[mt][2] = As_hi[buf][r0][qid + 4];      al[mt][2] = As_lo[buf][r0][qid + 4];
                ah[mt][3] = As_hi[buf][r0 + 8][qid + 4];  al[mt][3] = As_lo[buf][r0 + 8][qid + 4];
            }
#pragma unroll
            for (int nt = 0; nt < 4; nt++) {
                int n0 = warpN * 32 + nt * 8 + grp;
                bh[nt][0] = Bs_hi[buf][qid][n0];     bl[nt][0] = Bs_lo[buf][qid][n0];
                bh[nt][1] = Bs_hi[buf][qid + 4][n0]; bl[nt][1] = Bs_lo[buf][qid + 4][n0];
            }
#pragma unroll
            for (int mt = 0; mt < 2; mt++)
#pragma unroll
                for (int nt = 0; nt < 4; nt++) {
                    mma_tf32(acc[mt][nt], ah[mt], bh[nt]);
                    mma_tf32(acc[mt][nt], ah[mt], bl[nt]);
                    mma_tf32(acc[mt][nt], al[mt], bh[nt]);
                }
        }
        if (stage + 1 < 128 / BK) stStage(buf ^ 1);
        __syncthreads();
    }

#pragma unroll
    for (int mt = 0; mt < 2; mt++)
#pragma unroll
        for (int nt = 0; nt < 4; nt++) {
            int r0 = rowBase + warpM * 32 + mt * 16 + grp;
            int cc = colBase + warpN * 32 + nt * 8 + qid * 2;
            if (r0 < M)
                *(float2*)&C[(size_t)r0 * NC + cc] =
                    make_float2(acc[mt][nt][0], acc[mt][nt][1]);
            if (r0 + 8 < M)
                *(float2*)&C[(size_t)(r0 + 8) * NC + cc] =
                    make_float2(acc[mt][nt][2], acc[mt][nt][3]);
        }
}

// ---------------- layer-1 gather: warp per node, fused self-loop+bias+relu ----
__global__ __launch_bounds__(256)
void gather1_kernel(const float* __restrict__ b1, float* __restrict__ emb_out, int N) {
    int warp = (blockIdx.x * blockDim.x + threadIdx.x) >> 5;
    int lane = threadIdx.x & 31;
    if (warp >= N) return;
    const int i = warp;
    const int start = g_rowptr[i], end = g_rowptr[i + 1];
    const float di = g_dinv[i];

    float4 acc = *(const float4*)&g_h[(size_t)i * 128 + lane * 4];
    float d2 = di * di;
    acc.x *= d2; acc.y *= d2; acc.z *= d2; acc.w *= d2;

    for (int base = start; base < end; base += 32) {
        int rem = end - base;
        int cnt = rem < 32 ? rem : 32;
        int   myidx = (lane < cnt) ? g_csr_src[base + lane] : 0;
        float myw   = (lane < cnt) ? di * g_dinv[myidx] : 0.f;
        for (int j = 0; j < cnt; j++) {
            int   s = __shfl_sync(0xFFFFFFFFu, myidx, j);
            float w = __shfl_sync(0xFFFFFFFFu, myw, j);
            float4 v = *(const float4*)&g_h[(size_t)s * 128 + lane * 4];
            acc.x += v.x * w; acc.y += v.y * w; acc.z += v.z * w; acc.w += v.w * w;
        }
    }
    float4 bv = *(const float4*)&b1[lane * 4];
    acc.x = fmaxf(acc.x + bv.x, 0.f);
    acc.y = fmaxf(acc.y + bv.y, 0.f);
    acc.z = fmaxf(acc.z + bv.z, 0.f);
    acc.w = fmaxf(acc.w + bv.w, 0.f);
    *(float4*)&g_emb[(size_t)i * 128 + lane * 4] = acc;
    if (emb_out) *(float4*)&emb_out[(size_t)i * 128 + lane * 4] = acc;
}

// ---------------- layer-2 gather: warp per node, fused bias+log_softmax -------
__global__ __launch_bounds__(256)
void gather2_kernel(const float* __restrict__ b2, float* __restrict__ out, int N) {
    int warp = (blockIdx.x * blockDim.x + threadIdx.x) >> 5;
    int lane = threadIdx.x & 31;
    if (warp >= N) return;
    const int i = warp;
    const int start = g_rowptr[i], end = g_rowptr[i + 1];
    const float di = g_dinv[i];

    float2 acc = *(const float2*)&g_h2[(size_t)i * 64 + lane * 2];
    float d2 = di * di;
    acc.x *= d2; acc.y *= d2;

    for (int base = start; base < end; base += 32) {
        int rem = end - base;
        int cnt = rem < 32 ? rem : 32;
        int   myidx = (lane < cnt) ? g_csr_src[base + lane] : 0;
        float myw   = (lane < cnt) ? di * g_dinv[myidx] : 0.f;
        for (int j = 0; j < cnt; j++) {
            int   s = __shfl_sync(0xFFFFFFFFu, myidx, j);
            float w = __shfl_sync(0xFFFFFFFFu, myw, j);
            float2 v = *(const float2*)&g_h2[(size_t)s * 64 + lane * 2];
            acc.x += v.x * w; acc.y += v.y * w;
        }
    }
    float2 bv = *(const float2*)&b2[lane * 2];
    acc.x += bv.x; acc.y += bv.y;

    float m = fmaxf(acc.x, acc.y);
#pragma unroll
    for (int o = 16; o > 0; o >>= 1) m = fmaxf(m, __shfl_xor_sync(0xFFFFFFFFu, m, o));
    float sm = __expf(acc.x - m) + __expf(acc.y - m);
#pragma unroll
    for (int o = 16; o > 0; o >>= 1) sm += __shfl_xor_sync(0xFFFFFFFFu, sm, o);
    float lse = m + logf(sm);
    *(float2*)&out[(size_t)i * 64 + lane * 2] = make_float2(acc.x - lse, acc.y - lse);
}

extern "C" void kernel_launch(void* const* d_in, const int* in_sizes, int n_in,
                              void* d_out, int out_size) {
    const float* x  = (const float*)d_in[0];
    const void*  ei = d_in[1];
    const float* W1 = (const float*)d_in[2];
    const float* b1 = (const float*)d_in[3];
    const float* W2 = (const float*)d_in[4];
    const float* b2 = (const float*)d_in[5];
    const int N = in_sizes[0] / FIN;
    const int E = in_sizes[1] / 2;

    float* out_ls  = (float*)d_out;
    float* out_emb = (out_size >= N * (CLS + HID)) ? out_ls + (size_t)N * CLS : nullptr;

    static float* s_h   = nullptr;
    static float* s_emb = nullptr;
    static float* s_h2  = nullptr;
    if (!s_h) {
        cudaGetSymbolAddress((void**)&s_h,   g_h);
        cudaGetSymbolAddress((void**)&s_emb, g_emb);
        cudaGetSymbolAddress((void**)&s_h2,  g_h2);
    }

    const int T = 256;
    const int nScanBlocks = (N + 1023) / 1024;

    // #1..#3: setup
    detect_idx_kernel<<<1, 32>>>(ei, E, N);
    zero_deg_kernel<<<(N + T - 1) / T, T>>>(N);
    deg_kernel<<<(E + T - 1) / T, T>>>(ei, E, N);

    // #4: h = x @ W1  (slot 4 = the launch ncu captures)
    {
        dim3 grid((N + 127) / 128, HID / 64);
        gemm_tc<HID><<<grid, T>>>(x, W1, s_h, N);
    }

    // #5..#8: CSR build
    scan1_kernel<<<nScanBlocks, 1024>>>(N);
    scan2_kernel<<<1, 1024>>>(nScanBlocks);
    scan3_kernel<<<(N + T - 1) / T, T>>>(N);
    fill_csr_kernel<<<(E + T - 1) / T, T>>>(ei, E, N);

    // #9: layer-1 gather (fused self-loop + bias + relu) -> emb
    {
        long long threads = (long long)N * 32;
        gather1_kernel<<<(int)((threads + T - 1) / T), T>>>(b1, out_emb, N);
    }

    // #10: h2 = emb @ W2
    {
        dim3 grid((N + 127) / 128, CLS / 64);
        gemm_tc<CLS><<<grid, T>>>(s_emb, W2, s_h2, N);
    }

    // #11: layer-2 gather (fused self-loop + bias + log_softmax) -> out
    {
        long long threads = (long long)N * 32;
        gather2_kernel<<<(int)((threads + T - 1) / T), T>>>(b2, out_ls, N);
    }
}

// round 13
// speedup vs baseline: 1.0872x; 1.0872x over previous
#include <cuda_runtime.h>
#include <math.h>

#define NNODES 100000
#define FIN    128
#define HID    128
#define CLS    64
#define EMAX   2000000

// ---------------- static device scratch ----------------
__device__ float g_h   [(size_t)NNODES * HID];
__device__ float g_emb [(size_t)NNODES * HID];
__device__ float g_h2  [(size_t)NNODES * CLS];
__device__ float g_dinv[NNODES];
__device__ int   g_deg [NNODES];
__device__ int   g_incl[NNODES];
__device__ int   g_bsum[256];
__device__ int   g_rowptr[NNODES + 1];
__device__ int   g_cursor[NNODES];
__device__ int   g_csr_src[EMAX];
__device__ int   g_idx64;

// ---------------- edge-index dtype detection ----------------
__global__ void detect_idx_kernel(const void* __restrict__ ei, int E, int N) {
    if (threadIdx.x != 0 || blockIdx.x != 0) return;
    const long long* p64 = (const long long*)ei;
    int ok = 1;
    for (int i = 0; i < 128 && i < E; i++) {
        long long a = p64[i];
        long long b = p64[(size_t)E + i];
        if (a < 0 || a >= N || b < 0 || b >= N) { ok = 0; break; }
    }
    g_idx64 = ok;
}

__device__ __forceinline__ int fetch_idx(const void* __restrict__ ei, size_t i) {
    if (g_idx64) return (int)((const long long*)ei)[i];
    return ((const int*)ei)[i];
}

__global__ void zero_deg_kernel(int N) {
    int i = blockIdx.x * blockDim.x + threadIdx.x;
    if (i < N) g_deg[i] = 0;
}

__global__ void deg_kernel(const void* __restrict__ ei, int E, int N) {
    int i = blockIdx.x * blockDim.x + threadIdx.x;
    if (i >= E) return;
    int d = fetch_idx(ei, (size_t)E + i);
    if ((unsigned)d < (unsigned)N) atomicAdd(&g_deg[d], 1);
}

// ---------------- prefix scan over degrees ----------------
__global__ __launch_bounds__(1024) void scan1_kernel(int N) {
    __shared__ int sh[1024];
    int i = blockIdx.x * 1024 + threadIdx.x;
    int v = (i < N) ? g_deg[i] : 0;
    sh[threadIdx.x] = v;
    __syncthreads();
    for (int off = 1; off < 1024; off <<= 1) {
        int t = (threadIdx.x >= off) ? sh[threadIdx.x - off] : 0;
        __syncthreads();
        sh[threadIdx.x] += t;
        __syncthreads();
    }
    if (i < N) g_incl[i] = sh[threadIdx.x];
    if (threadIdx.x == 1023) g_bsum[blockIdx.x] = sh[1023];
}

__global__ __launch_bounds__(1024) void scan2_kernel(int nb) {
    __shared__ int sh[1024];
    int v = (threadIdx.x < nb) ? g_bsum[threadIdx.x] : 0;
    sh[threadIdx.x] = v;
    __syncthreads();
    for (int off = 1; off < 1024; off <<= 1) {
        int t = (threadIdx.x >= off) ? sh[threadIdx.x - off] : 0;
        __syncthreads();
        sh[threadIdx.x] += t;
        __syncthreads();
    }
    if (threadIdx.x < nb)
        g_bsum[threadIdx.x] = (threadIdx.x == 0) ? 0 : sh[threadIdx.x - 1];
}

__global__ void scan3_kernel(int N) {
    int i = blockIdx.x * blockDim.x + threadIdx.x;
    if (i >= N) return;
    int deg = g_deg[i];
    int v = g_incl[i] + g_bsum[i >> 10];
    g_rowptr[i + 1] = v;
    g_cursor[i] = v - deg;
    g_dinv[i] = rsqrtf((float)(deg + 1));
    if (i == 0) g_rowptr[0] = 0;
}

__global__ void fill_csr_kernel(const void* __restrict__ ei, int E, int N) {
    int e = blockIdx.x * blockDim.x + threadIdx.x;
    if (e >= E) return;
    int s = fetch_idx(ei, e);
    int d = fetch_idx(ei, (size_t)E + e);
    if ((unsigned)s >= (unsigned)N || (unsigned)d >= (unsigned)N) return;
    int pos = atomicAdd(&g_cursor[d], 1);
    if (pos < EMAX) g_csr_src[pos] = s;
}

// ---------------- tensor-core helpers (3xtf32) ----------------
__device__ __forceinline__ void split_tf32(float v, unsigned& hi, unsigned& lo) {
    asm("cvt.rna.tf32.f32 %0, %1;" : "=r"(hi) : "f"(v));
    float r = v - __uint_as_float(hi);
    asm("cvt.rna.tf32.f32 %0, %1;" : "=r"(lo) : "f"(r));
}

__device__ __forceinline__ void mma_tf32(float* d, const unsigned* a, const unsigned* b) {
    asm volatile(
        "mma.sync.aligned.m16n8k8.row.col.f32.tf32.tf32.f32 "
        "{%0,%1,%2,%3}, {%4,%5,%6,%7}, {%8,%9}, {%0,%1,%2,%3};"
        : "+f"(d[0]), "+f"(d[1]), "+f"(d[2]), "+f"(d[3])
        : "r"(a[0]), "r"(a[1]), "r"(a[2]), "r"(a[3]), "r"(b[0]), "r"(b[1]));
}

// ---------------- GEMM via tensor cores, 3xtf32 ----------------
// C[M,NC] = A[M,128] @ B[128,NC].  Block tile 128x64, 128 threads = 4 warps,
// warp tile 32x64 (mt=2 m16, nt=8 n8), BK=8 double-buffered, 16 stages.
// A kept fp32 in smem, split in-loop (each element split by ONE warp).
// B pre-split hi/lo in smem (kills 4x per-warp split redundancy).
template <int NC>
__global__ __launch_bounds__(128)
void gemm_tc(const float* __restrict__ A, const float* __restrict__ B,
             float* __restrict__ C, int M) {
    constexpr int BK = 8;
    constexpr int ASTR = 12;   // (12*grp+qid) mod 32: all 32 banks distinct
    constexpr int BSTR = 72;   // (8*qid+grp) mod 32: distinct
    __shared__ float    As  [2][128][ASTR];
    __shared__ unsigned Bs_h[2][BK][BSTR];
    __shared__ unsigned Bs_l[2][BK][BSTR];

    const int t    = threadIdx.x;
    const int lane = t & 31;
    const int grp  = lane >> 2, qid = lane & 3;
    const int warpM = t >> 5;                 // 0..3
    const int rowBase = blockIdx.x * 128;
    const int colBase = blockIdx.y * 64;

    float acc[2][8][4];
#pragma unroll
    for (int mt = 0; mt < 2; mt++)
#pragma unroll
        for (int nt = 0; nt < 8; nt++)
#pragma unroll
            for (int k = 0; k < 4; k++) acc[mt][nt][k] = 0.f;

    // A: 128 rows x 8 k = 256 float4, 128 thr -> 2 each.  B: 8 x 64 = 128 float4 -> 1 each.
    float4 sa[2], sb;
    const int bRow = t >> 4, bC4 = (t & 15) * 4;

    auto ldA = [&](int k0) {
#pragma unroll
        for (int i = 0; i < 2; i++) {
            int idx = t + 128 * i;
            int r = rowBase + (idx >> 1);
            int c = (idx & 1) * 4;
            sa[i] = (r < M) ? *(const float4*)&A[(size_t)r * 128 + k0 + c]
                            : make_float4(0.f, 0.f, 0.f, 0.f);
        }
    };
    auto ldB4 = [&](int k0) {
        sb = *(const float4*)&B[(size_t)(k0 + bRow) * NC + colBase + bC4];
    };
    auto stStage = [&](int buf) {
#pragma unroll
        for (int i = 0; i < 2; i++) {
            int idx = t + 128 * i;
            int row = idx >> 1, c = (idx & 1) * 4;
            *(float4*)&As[buf][row][c] = sa[i];
        }
        float vb[4] = {sb.x, sb.y, sb.z, sb.w};
#pragma unroll
        for (int j = 0; j < 4; j++)
            split_tf32(vb[j], Bs_h[buf][bRow][bC4 + j], Bs_l[buf][bRow][bC4 + j]);
    };

    ldA(0); ldB4(0);
    stStage(0);
    __syncthreads();

    for (int stage = 0; stage < 128 / BK; stage++) {
        const int buf = stage & 1;
        if (stage + 1 < 128 / BK) { ldA((stage + 1) * BK); ldB4((stage + 1) * BK); }

        unsigned ah[2][4], al[2][4];
#pragma unroll
        for (int mt = 0; mt < 2; mt++) {
            int r0 = warpM * 32 + mt * 16 + grp;
            split_tf32(As[buf][r0][qid],          ah[mt][0], al[mt][0]);
            split_tf32(As[buf][r0 + 8][qid],      ah[mt][1], al[mt][1]);
            split_tf32(As[buf][r0][qid + 4],      ah[mt][2], al[mt][2]);
            split_tf32(As[buf][r0 + 8][qid + 4],  ah[mt][3], al[mt][3]);
        }
#pragma unroll
        for (int half = 0; half < 2; half++) {
            unsigned bh[4][2], bl[4][2];
#pragma unroll
            for (int j = 0; j < 4; j++) {
                int n0 = (half * 4 + j) * 8 + grp;
                bh[j][0] = Bs_h[buf][qid][n0];     bl[j][0] = Bs_l[buf][qid][n0];
                bh[j][1] = Bs_h[buf][qid + 4][n0]; bl[j][1] = Bs_l[buf][qid + 4][n0];
            }
#pragma unroll
            for (int mt = 0; mt < 2; mt++)
#pragma unroll
                for (int j = 0; j < 4; j++) {
                    float* d = acc[mt][half * 4 + j];
                    mma_tf32(d, ah[mt], bh[j]);
                    mma_tf32(d, ah[mt], bl[j]);
                    mma_tf32(d, al[mt], bh[j]);
                }
        }
        if (stage + 1 < 128 / BK) stStage(buf ^ 1);
        __syncthreads();
    }

#pragma unroll
    for (int mt = 0; mt < 2; mt++)
#pragma unroll
        for (int nt = 0; nt < 8; nt++) {
            int r0 = rowBase + warpM * 32 + mt * 16 + grp;
            int cc = colBase + nt * 8 + qid * 2;
            if (r0 < M)
                *(float2*)&C[(size_t)r0 * NC + cc] =
                    make_float2(acc[mt][nt][0], acc[mt][nt][1]);
            if (r0 + 8 < M)
                *(float2*)&C[(size_t)(r0 + 8) * NC + cc] =
                    make_float2(acc[mt][nt][2], acc[mt][nt][3]);
        }
}

// ---------------- layer-1 gather: warp per node, fused self-loop+bias+relu ----
__global__ __launch_bounds__(256)
void gather1_kernel(const float* __restrict__ b1, float* __restrict__ emb_out, int N) {
    int warp = (blockIdx.x * blockDim.x + threadIdx.x) >> 5;
    int lane = threadIdx.x & 31;
    if (warp >= N) return;
    const int i = warp;
    const int start = g_rowptr[i], end = g_rowptr[i + 1];
    const float di = g_dinv[i];

    float4 acc = *(const float4*)&g_h[(size_t)i * 128 + lane * 4];
    float d2 = di * di;
    acc.x *= d2; acc.y *= d2; acc.z *= d2; acc.w *= d2;

    for (int base = start; base < end; base += 32) {
        int rem = end - base;
        int cnt = rem < 32 ? rem : 32;
        int   myidx = (lane < cnt) ? g_csr_src[base + lane] : 0;
        float myw   = (lane < cnt) ? di * g_dinv[myidx] : 0.f;
        for (int j = 0; j < cnt; j++) {
            int   s = __shfl_sync(0xFFFFFFFFu, myidx, j);
            float w = __shfl_sync(0xFFFFFFFFu, myw, j);
            float4 v = *(const float4*)&g_h[(size_t)s * 128 + lane * 4];
            acc.x += v.x * w; acc.y += v.y * w; acc.z += v.z * w; acc.w += v.w * w;
        }
    }
    float4 bv = *(const float4*)&b1[lane * 4];
    acc.x = fmaxf(acc.x + bv.x, 0.f);
    acc.y = fmaxf(acc.y + bv.y, 0.f);
    acc.z = fmaxf(acc.z + bv.z, 0.f);
    acc.w = fmaxf(acc.w + bv.w, 0.f);
    *(float4*)&g_emb[(size_t)i * 128 + lane * 4] = acc;
    if (emb_out) *(float4*)&emb_out[(size_t)i * 128 + lane * 4] = acc;
}

// ---------------- layer-2 gather: warp per node, fused bias+log_softmax -------
__global__ __launch_bounds__(256)
void gather2_kernel(const float* __restrict__ b2, float* __restrict__ out, int N) {
    int warp = (blockIdx.x * blockDim.x + threadIdx.x) >> 5;
    int lane = threadIdx.x & 31;
    if (warp >= N) return;
    const int i = warp;
    const int start = g_rowptr[i], end = g_rowptr[i + 1];
    const float di = g_dinv[i];

    float2 acc = *(const float2*)&g_h2[(size_t)i * 64 + lane * 2];
    float d2 = di * di;
    acc.x *= d2; acc.y *= d2;

    for (int base = start; base < end; base += 32) {
        int rem = end - base;
        int cnt = rem < 32 ? rem : 32;
        int   myidx = (lane < cnt) ? g_csr_src[base + lane] : 0;
        float myw   = (lane < cnt) ? di * g_dinv[myidx] : 0.f;
        for (int j = 0; j < cnt; j++) {
            int   s = __shfl_sync(0xFFFFFFFFu, myidx, j);
            float w = __shfl_sync(0xFFFFFFFFu, myw, j);
            float2 v = *(const float2*)&g_h2[(size_t)s * 64 + lane * 2];
            acc.x += v.x * w; acc.y += v.y * w;
        }
    }
    float2 bv = *(const float2*)&b2[lane * 2];
    acc.x += bv.x; acc.y += bv.y;

    float m = fmaxf(acc.x, acc.y);
#pragma unroll
    for (int o = 16; o > 0; o >>= 1) m = fmaxf(m, __shfl_xor_sync(0xFFFFFFFFu, m, o));
    float sm = __expf(acc.x - m) + __expf(acc.y - m);
#pragma unroll
    for (int o = 16; o > 0; o >>= 1) sm += __shfl_xor_sync(0xFFFFFFFFu, sm, o);
    float lse = m + logf(sm);
    *(float2*)&out[(size_t)i * 64 + lane * 2] = make_float2(acc.x - lse, acc.y - lse);
}

extern "C" void kernel_launch(void* const* d_in, const int* in_sizes, int n_in,
                              void* d_out, int out_size) {
    const float* x  = (const float*)d_in[0];
    const void*  ei = d_in[1];
    const float* W1 = (const float*)d_in[2];
    const float* b1 = (const float*)d_in[3];
    const float* W2 = (const float*)d_in[4];
    const float* b2 = (const float*)d_in[5];
    const int N = in_sizes[0] / FIN;
    const int E = in_sizes[1] / 2;

    float* out_ls  = (float*)d_out;
    float* out_emb = (out_size >= N * (CLS + HID)) ? out_ls + (size_t)N * CLS : nullptr;

    static float* s_h   = nullptr;
    static float* s_emb = nullptr;
    static float* s_h2  = nullptr;
    if (!s_h) {
        cudaGetSymbolAddress((void**)&s_h,   g_h);
        cudaGetSymbolAddress((void**)&s_emb, g_emb);
        cudaGetSymbolAddress((void**)&s_h2,  g_h2);
    }

    const int T = 256;
    const int nScanBlocks = (N + 1023) / 1024;

    // #1..#3: setup
    detect_idx_kernel<<<1, 32>>>(ei, E, N);
    zero_deg_kernel<<<(N + T - 1) / T, T>>>(N);
    deg_kernel<<<(E + T - 1) / T, T>>>(ei, E, N);

    // #4: h = x @ W1  (slot 4 = the launch ncu captures)
    {
        dim3 grid((N + 127) / 128, HID / 64);
        gemm_tc<HID><<<grid, 128>>>(x, W1, s_h, N);
    }

    // #5..#8: CSR build
    scan1_kernel<<<nScanBlocks, 1024>>>(N);
    scan2_kernel<<<1, 1024>>>(nScanBlocks);
    scan3_kernel<<<(N + T - 1) / T, T>>>(N);
    fill_csr_kernel<<<(E + T - 1) / T, T>>>(ei, E, N);

    // #9: layer-1 gather (fused self-loop + bias + relu) -> emb
    {
        long long threads = (long long)N * 32;
        gather1_kernel<<<(int)((threads + T - 1) / T), T>>>(b1, out_emb, N);
    }

    // #10: h2 = emb @ W2
    {
        dim3 grid((N + 127) / 128, CLS / 64);
        gemm_tc<CLS><<<grid, 128>>>(s_emb, W2, s_h2, N);
    }

    // #11: layer-2 gather (fused self-loop + bias + log_softmax) -> out
    {
        long long threads = (long long)N * 32;
        gather2_kernel<<<(int)((threads + T - 1) / T), T>>>(b2, out_ls, N);
    }
}